// round 1
// baseline (speedup 1.0000x reference)
#include <cuda_runtime.h>

// Rotated ROI cropper:
//   x:     [8, 3, 1024, 1024] fp32
//   boxes: [8, 64, 5] fp32  (cx, cy, w, h, angle_deg)
//   out:   [512, 3, 48, 320] fp32
//
// One block per (box, output row). 320 threads = one output row.
// Each thread computes the affine source coord + bilinear weights once,
// then samples all 3 channels (reusing addresses/weights).

#define IMG_H 1024
#define IMG_W 1024
#define OUT_H 48
#define OUT_W 320
#define N_BOXES_TOTAL 512
#define CHANS 3

__global__ __launch_bounds__(OUT_W)
void rotated_roi_crop_kernel(const float* __restrict__ x,
                             const float* __restrict__ boxes,
                             float* __restrict__ out) {
    const int row = blockIdx.x % OUT_H;        // 0..47
    const int g   = blockIdx.x / OUT_H;        // global box id 0..511
    const int tx  = threadIdx.x;               // 0..319

    // Box params (uniform broadcast loads)
    const float* bp = boxes + g * 5;
    const float cx  = bp[0];
    const float cy  = bp[1];
    const float bw  = bp[2];
    const float bh  = bp[3];
    const float ang = bp[4];

    // cv2 rect corner math (matches reference exactly)
    const float theta = -ang * 0.017453292519943295f;  // pi/180
    float s_, c_;
    sincosf(theta, &s_, &c_);
    const float b = c_ * 0.5f;
    const float a = s_ * 0.5f;

    const float p0x = cx - a * bh - b * bw;
    const float p0y = cy + b * bh - a * bw;
    const float p1x = cx + a * bh - b * bw;
    const float p1y = cy - b * bh - a * bw;
    const float p2x = 2.0f * cx - p0x;
    const float p2y = 2.0f * cy - p0y;

    const float u = (float)tx  / (float)OUT_W;
    const float v = (float)row / (float)OUT_H;

    const float sx = p1x + u * (p2x - p1x) + v * (p0x - p1x);
    const float sy = p1y + u * (p2y - p1y) + v * (p0y - p1y);

    const float x0f = floorf(sx);
    const float y0f = floorf(sy);
    const float dx = sx - x0f;
    const float dy = sy - y0f;
    const int x0 = (int)x0f;
    const int y0 = (int)y0f;
    const int x1 = x0 + 1;
    const int y1 = y0 + 1;

    // Validity folded into weights (zero padding outside image)
    const bool vx0 = (x0 >= 0) & (x0 < IMG_W);
    const bool vx1 = (x1 >= 0) & (x1 < IMG_W);
    const bool vy0 = (y0 >= 0) & (y0 < IMG_H);
    const bool vy1 = (y1 >= 0) & (y1 < IMG_H);

    float w00 = (1.0f - dx) * (1.0f - dy); w00 = (vx0 & vy0) ? w00 : 0.0f;
    float w10 = dx * (1.0f - dy);          w10 = (vx1 & vy0) ? w10 : 0.0f;
    float w01 = (1.0f - dx) * dy;          w01 = (vx0 & vy1) ? w01 : 0.0f;
    float w11 = dx * dy;                   w11 = (vx1 & vy1) ? w11 : 0.0f;

    // Clamped coords — loads are always in-bounds; weights kill invalid taps
    const int xc0 = min(max(x0, 0), IMG_W - 1);
    const int xc1 = min(max(x1, 0), IMG_W - 1);
    const int yc0 = min(max(y0, 0), IMG_H - 1);
    const int yc1 = min(max(y1, 0), IMG_H - 1);

    const int o00 = yc0 * IMG_W + xc0;
    const int o10 = yc0 * IMG_W + xc1;
    const int o01 = yc1 * IMG_W + xc0;
    const int o11 = yc1 * IMG_W + xc1;

    const int batch = g >> 6;  // g / 64
    const float* img = x + (size_t)batch * CHANS * IMG_H * IMG_W;

    float* op = out + ((size_t)g * CHANS) * (OUT_H * OUT_W) + row * OUT_W + tx;

#pragma unroll
    for (int c = 0; c < CHANS; c++) {
        const float* p = img + (size_t)c * (IMG_H * IMG_W);
        float val = __ldg(p + o00) * w00
                  + __ldg(p + o10) * w10
                  + __ldg(p + o01) * w01
                  + __ldg(p + o11) * w11;
        op[(size_t)c * (OUT_H * OUT_W)] = val;
    }
}

extern "C" void kernel_launch(void* const* d_in, const int* in_sizes, int n_in,
                              void* d_out, int out_size) {
    const float* x     = (const float*)d_in[0];
    const float* boxes = (const float*)d_in[1];
    float* out         = (float*)d_out;

    dim3 grid(N_BOXES_TOTAL * OUT_H);
    dim3 block(OUT_W);
    rotated_roi_crop_kernel<<<grid, block>>>(x, boxes, out);
}

// round 2
// speedup vs baseline: 1.0513x; 1.0513x over previous
#include <cuda_runtime.h>

// Rotated ROI cropper, smem-staged:
//   x:     [8, 3, 1024, 1024] fp32
//   boxes: [8, 64, 5] fp32  (cx, cy, w, h, angle_deg)
//   out:   [512, 3, 48, 320] fp32
//
// Block = one 32x16 output tile of one box. The source-space bounding box of
// that tile is <= 37x36 px (given bw<300, bh<60, |ang|<=45), staged in smem
// for all 3 channels; taps are LDS, gmem reads are coalesced row segments
// loaded once per block.

#define IMG_H 1024
#define IMG_W 1024
#define OUT_H 48
#define OUT_W 320
#define CHANS 3
#define N_BOXES_TOTAL 512

#define TILE_OX 32
#define TILE_OY 16
#define NTX (OUT_W / TILE_OX)   // 10
#define NTY (OUT_H / TILE_OY)   // 3

#define STILE  38               // smem tile side (source px)
#define SPITCH 39               // odd pitch -> good bank spread on diagonals

#define NTHREADS 256

__global__ __launch_bounds__(NTHREADS)
void rotated_roi_crop_smem(const float* __restrict__ x,
                           const float* __restrict__ boxes,
                           float* __restrict__ out) {
    __shared__ float tile[CHANS][STILE][SPITCH];

    const int bid     = blockIdx.x;
    const int tx_tile = bid % NTX;
    const int ty_tile = (bid / NTX) % NTY;
    const int g       = bid / (NTX * NTY);      // global box id 0..511

    // ---- box params (uniform broadcast) ----
    const float* bp = boxes + g * 5;
    const float cx  = bp[0];
    const float cy  = bp[1];
    const float bw  = bp[2];
    const float bh  = bp[3];
    const float ang = bp[4];

    const float theta = -ang * 0.017453292519943295f;
    float s_, c_;
    sincosf(theta, &s_, &c_);
    const float b = c_ * 0.5f;
    const float a = s_ * 0.5f;

    const float p0x = cx - a * bh - b * bw;
    const float p0y = cy + b * bh - a * bw;
    const float p1x = cx + a * bh - b * bw;
    const float p1y = cy - b * bh - a * bw;
    const float p2x = 2.0f * cx - p0x;
    const float p2y = 2.0f * cy - p0y;

    const float ex_x = p2x - p1x;   // source step per unit u
    const float ex_y = p2y - p1y;
    const float ey_x = p0x - p1x;   // source step per unit v
    const float ey_y = p0y - p1y;

    // ---- source-space bbox of this output tile (corners of affine map) ----
    const float u0 = (float)(tx_tile * TILE_OX)               / (float)OUT_W;
    const float u1 = (float)(tx_tile * TILE_OX + TILE_OX - 1) / (float)OUT_W;
    const float v0 = (float)(ty_tile * TILE_OY)               / (float)OUT_H;
    const float v1 = (float)(ty_tile * TILE_OY + TILE_OY - 1) / (float)OUT_H;

    const float sxa = p1x + u0 * ex_x + v0 * ey_x;
    const float sxb = p1x + u1 * ex_x + v0 * ey_x;
    const float sxc = p1x + u0 * ex_x + v1 * ey_x;
    const float sxd = p1x + u1 * ex_x + v1 * ey_x;
    const float sya = p1y + u0 * ex_y + v0 * ey_y;
    const float syb = p1y + u1 * ex_y + v0 * ey_y;
    const float syc = p1y + u0 * ex_y + v1 * ey_y;
    const float syd = p1y + u1 * ex_y + v1 * ey_y;

    const float min_sx = fminf(fminf(sxa, sxb), fminf(sxc, sxd));
    const float max_sx = fmaxf(fmaxf(sxa, sxb), fmaxf(sxc, sxd));
    const float min_sy = fminf(fminf(sya, syb), fminf(syc, syd));
    const float max_sy = fmaxf(fmaxf(sya, syb), fmaxf(syc, syd));

    const int x_org = (int)floorf(min_sx);
    const int y_org = (int)floorf(min_sy);
    // indices needed: [x_org, floor(max_sx)+1] inclusive
    const int bwid = min((int)floorf(max_sx) + 2 - x_org, STILE);
    const int bhei = min((int)floorf(max_sy) + 2 - y_org, STILE);

    // ---- cooperative staged load (all 3 channels), zero-fill outside ----
    const int batch = g >> 6;
    const float* img = x + (size_t)batch * CHANS * IMG_H * IMG_W;

    const int nelem = STILE * bhei;
    for (int i = threadIdx.x; i < nelem; i += NTHREADS) {
        const int yy = i / STILE;
        const int xx = i - yy * STILE;
        const int gx = x_org + xx;
        const int gy = y_org + yy;
        const bool ok = ((unsigned)gx < IMG_W) & ((unsigned)gy < IMG_H) & (xx < bwid);
        const float* p = img + (size_t)gy * IMG_W + gx;
        float v0c = 0.0f, v1c = 0.0f, v2c = 0.0f;
        if (ok) {
            v0c = __ldg(p);
            v1c = __ldg(p + IMG_H * IMG_W);
            v2c = __ldg(p + 2 * IMG_H * IMG_W);
        }
        tile[0][yy][xx] = v0c;
        tile[1][yy][xx] = v1c;
        tile[2][yy][xx] = v2c;
    }
    __syncthreads();

    // ---- compute: warp = 32 contiguous output px; each thread 2 rows ----
    const int lane = threadIdx.x & 31;
    const int wrp  = threadIdx.x >> 5;    // 0..7

    const int ox = tx_tile * TILE_OX + lane;
    const float u = (float)ox / (float)OUT_W;
    const float sxu = fmaf(u, ex_x, p1x);
    const float syu = fmaf(u, ex_y, p1y);

#pragma unroll
    for (int r = 0; r < 2; r++) {
        const int oy = ty_tile * TILE_OY + wrp * 2 + r;
        const float v = (float)oy / (float)OUT_H;
        const float sx = fmaf(v, ey_x, sxu);
        const float sy = fmaf(v, ey_y, syu);

        const float x0f = floorf(sx);
        const float y0f = floorf(sy);
        const float dx = sx - x0f;
        const float dy = sy - y0f;

        int lx = (int)x0f - x_org;
        int ly = (int)y0f - y_org;
        lx = min(max(lx, 0), STILE - 2);   // safety clamp (never binds in-spec)
        ly = min(max(ly, 0), STILE - 2);

        const float w00 = (1.0f - dx) * (1.0f - dy);
        const float w10 = dx * (1.0f - dy);
        const float w01 = (1.0f - dx) * dy;
        const float w11 = dx * dy;

        float* ob = out + (((size_t)g * CHANS) * OUT_H + oy) * OUT_W + ox;
#pragma unroll
        for (int c = 0; c < CHANS; c++) {
            const float* t = &tile[c][ly][lx];
            float val = t[0]          * w00
                      + t[1]          * w10
                      + t[SPITCH]     * w01
                      + t[SPITCH + 1] * w11;
            ob[(size_t)c * (OUT_H * OUT_W)] = val;
        }
    }
}

extern "C" void kernel_launch(void* const* d_in, const int* in_sizes, int n_in,
                              void* d_out, int out_size) {
    const float* x     = (const float*)d_in[0];
    const float* boxes = (const float*)d_in[1];
    float* out         = (float*)d_out;

    dim3 grid(N_BOXES_TOTAL * NTX * NTY);   // 15360
    dim3 block(NTHREADS);
    rotated_roi_crop_smem<<<grid, block>>>(x, boxes, out);
}